// round 7
// baseline (speedup 1.0000x reference)
#include <cuda_runtime.h>
#include <cstdint>

// MLPDecoder: out[e, :] = |input[r[e], :] - input[c[e], :]| @ weight[256, 4]
//
// Inputs (metadata order):
//   d_in[0]: input     float32 [100000, 256]
//   d_in[1]: r_indices int32   [500000]   (JAX x64 disabled -> int64 request
//   d_in[2]: c_indices int32   [500000]    silently becomes int32; confirmed
//                                          by the R1 OOB crash with int64 reads)
//   d_in[3]: weight    float32 [256, 4]
// Output: float32 [500000, 4]
//
// Strategy: warp-per-edge, grid-stride. Each lane covers 8 contiguous dims
// (2 x float4 per row). Weight rows for those dims live in registers for the
// warp's whole lifetime. L2-bandwidth-bound (~1 GB of gather reads; node
// table ~102 MB nearly fits the 126 MB L2).

#define D 256

__global__ __launch_bounds__(256, 3)
void edge_mlp_kernel(const float* __restrict__ input,
                     const int* __restrict__ r_indices,
                     const int* __restrict__ c_indices,
                     const float* __restrict__ weight,
                     float* __restrict__ out,
                     int n_edges)
{
    const int lane   = threadIdx.x & 31;
    const int gwarp  = (blockIdx.x * blockDim.x + threadIdx.x) >> 5;
    const int nwarps = (gridDim.x * blockDim.x) >> 5;

    // Lane l owns dims [8l, 8l+8). Load its 8 weight rows (each row = float4)
    // into registers once; reused for every edge this warp processes.
    const float4* w4 = reinterpret_cast<const float4*>(weight);
    float4 w[8];
    const int d0 = lane * 8;
#pragma unroll
    for (int j = 0; j < 8; j++) w[j] = w4[d0 + j];

    const float4* in4 = reinterpret_cast<const float4*>(input);

    for (int e = gwarp; e < n_edges; e += nwarps) {
        const long long r = (long long)__ldg(&r_indices[e]);
        const long long c = (long long)__ldg(&c_indices[e]);

        // row base in float4 units: node * (D/4); lane offset lane*2
        const float4* ra = in4 + r * (D / 4) + lane * 2;
        const float4* rb = in4 + c * (D / 4) + lane * 2;

        // 4 independent 128-bit loads -> MLP 4
        float4 a0 = ra[0];
        float4 a1 = ra[1];
        float4 b0 = rb[0];
        float4 b1 = rb[1];

        float dv[8];
        dv[0] = fabsf(a0.x - b0.x);
        dv[1] = fabsf(a0.y - b0.y);
        dv[2] = fabsf(a0.z - b0.z);
        dv[3] = fabsf(a0.w - b0.w);
        dv[4] = fabsf(a1.x - b1.x);
        dv[5] = fabsf(a1.y - b1.y);
        dv[6] = fabsf(a1.z - b1.z);
        dv[7] = fabsf(a1.w - b1.w);

        float acc0 = 0.f, acc1 = 0.f, acc2 = 0.f, acc3 = 0.f;
#pragma unroll
        for (int j = 0; j < 8; j++) {
            acc0 = fmaf(dv[j], w[j].x, acc0);
            acc1 = fmaf(dv[j], w[j].y, acc1);
            acc2 = fmaf(dv[j], w[j].z, acc2);
            acc3 = fmaf(dv[j], w[j].w, acc3);
        }

        // Warp reduction (4 independent trees -> good ILP on the shfl chain)
#pragma unroll
        for (int off = 16; off > 0; off >>= 1) {
            acc0 += __shfl_down_sync(0xFFFFFFFFu, acc0, off);
            acc1 += __shfl_down_sync(0xFFFFFFFFu, acc1, off);
            acc2 += __shfl_down_sync(0xFFFFFFFFu, acc2, off);
            acc3 += __shfl_down_sync(0xFFFFFFFFu, acc3, off);
        }

        if (lane == 0) {
            reinterpret_cast<float4*>(out)[e] =
                make_float4(acc0, acc1, acc2, acc3);
        }
    }
}

extern "C" void kernel_launch(void* const* d_in, const int* in_sizes, int n_in,
                              void* d_out, int out_size)
{
    const float* input  = (const float*)d_in[0];
    const int*   r_idx  = (const int*)d_in[1];
    const int*   c_idx  = (const int*)d_in[2];
    const float* weight = (const float*)d_in[3];
    float*       out    = (float*)d_out;

    const int n_edges = in_sizes[1];  // 500000

    // Grid-stride launch: 148 SMs * 16 blocks queued,
    // 256 threads (8 warps) per block, ~26 edges per warp.
    const int threads = 256;
    const int blocks  = 148 * 16;

    edge_mlp_kernel<<<blocks, threads>>>(input, r_idx, c_idx, weight, out,
                                         n_edges);
}

// round 12
// speedup vs baseline: 1.1875x; 1.1875x over previous
#include <cuda_runtime.h>
#include <cstdint>

// MLPDecoder: out[e, :] = |input[r[e], :] - input[c[e], :]| @ weight[256, 4]
//
//   d_in[0]: input     float32 [100000, 256]
//   d_in[1]: r_indices int32   [500000]
//   d_in[2]: c_indices int32   [500000]
//   d_in[3]: weight    float32 [256, 4]
// Output: float32 [500000, 4]
//
// R7 ncu: L1=81.8% (binding), L2=33%, DRAM=29%. Old lane->dim mapping
// (lane*32B stride) made every LDG.128 touch 8 lines half-densely:
// 32 wavefronts/edge = 2x minimum. This version uses lane-consecutive
// float4 loads: each warp load is 512B contiguous = 4 fully-dense lines.
// 16 wavefronts/edge = minimum. Lane l now owns dims [4l,4l+4) and
// [128+4l, 128+4l+4).

#define D 256

__global__ __launch_bounds__(256, 4)
void edge_mlp_kernel(const float* __restrict__ input,
                     const int* __restrict__ r_indices,
                     const int* __restrict__ c_indices,
                     const float* __restrict__ weight,
                     float* __restrict__ out,
                     int n_edges)
{
    const int lane   = threadIdx.x & 31;
    const int gwarp  = (blockIdx.x * blockDim.x + threadIdx.x) >> 5;
    const int nwarps = (gridDim.x * blockDim.x) >> 5;

    // Weight rows for this lane's dims, register-resident for the whole run.
    // w[0..3]  -> rows 4*lane + j          (first half of the row)
    // w[4..7]  -> rows 128 + 4*lane + j    (second half)
    const float4* w4 = reinterpret_cast<const float4*>(weight);
    float4 w[8];
#pragma unroll
    for (int j = 0; j < 4; j++) w[j]     = w4[4 * lane + j];
#pragma unroll
    for (int j = 0; j < 4; j++) w[4 + j] = w4[128 + 4 * lane + j];

    const float4* in4 = reinterpret_cast<const float4*>(input);

    for (int e = gwarp; e < n_edges; e += nwarps) {
        const long long r = (long long)__ldg(&r_indices[e]);
        const long long c = (long long)__ldg(&c_indices[e]);

        // Row base in float4 units (D/4 = 64 per row). Lane-consecutive
        // float4 loads: each warp-wide load covers 512B contiguous
        // (4 fully-dense 128B lines -> 4 L1 wavefronts).
        const float4* ra = in4 + r * (D / 4) + lane;
        const float4* rb = in4 + c * (D / 4) + lane;

        float4 a0 = ra[0];    // dims [4l, 4l+4)
        float4 a1 = ra[32];   // dims [128+4l, 128+4l+4)
        float4 b0 = rb[0];
        float4 b1 = rb[32];

        float dv[8];
        dv[0] = fabsf(a0.x - b0.x);
        dv[1] = fabsf(a0.y - b0.y);
        dv[2] = fabsf(a0.z - b0.z);
        dv[3] = fabsf(a0.w - b0.w);
        dv[4] = fabsf(a1.x - b1.x);
        dv[5] = fabsf(a1.y - b1.y);
        dv[6] = fabsf(a1.z - b1.z);
        dv[7] = fabsf(a1.w - b1.w);

        float acc0 = 0.f, acc1 = 0.f, acc2 = 0.f, acc3 = 0.f;
#pragma unroll
        for (int j = 0; j < 8; j++) {
            acc0 = fmaf(dv[j], w[j].x, acc0);
            acc1 = fmaf(dv[j], w[j].y, acc1);
            acc2 = fmaf(dv[j], w[j].z, acc2);
            acc3 = fmaf(dv[j], w[j].w, acc3);
        }

        // Warp reduction (4 independent trees -> ILP on the shfl chain)
#pragma unroll
        for (int off = 16; off > 0; off >>= 1) {
            acc0 += __shfl_down_sync(0xFFFFFFFFu, acc0, off);
            acc1 += __shfl_down_sync(0xFFFFFFFFu, acc1, off);
            acc2 += __shfl_down_sync(0xFFFFFFFFu, acc2, off);
            acc3 += __shfl_down_sync(0xFFFFFFFFu, acc3, off);
        }

        if (lane == 0) {
            reinterpret_cast<float4*>(out)[e] =
                make_float4(acc0, acc1, acc2, acc3);
        }
    }
}

extern "C" void kernel_launch(void* const* d_in, const int* in_sizes, int n_in,
                              void* d_out, int out_size)
{
    const float* input  = (const float*)d_in[0];
    const int*   r_idx  = (const int*)d_in[1];
    const int*   c_idx  = (const int*)d_in[2];
    const float* weight = (const float*)d_in[3];
    float*       out    = (float*)d_out;

    const int n_edges = in_sizes[1];  // 500000

    const int threads = 256;
    const int blocks  = 148 * 16;

    edge_mlp_kernel<<<blocks, threads>>>(input, r_idx, c_idx, weight, out,
                                         n_edges);
}

// round 17
// speedup vs baseline: 1.2242x; 1.0309x over previous
#include <cuda_runtime.h>
#include <cstdint>

// MLPDecoder: out[e, :] = |input[r[e], :] - input[c[e], :]| @ weight[256, 4]
//
//   d_in[0]: input     float32 [100000, 256]
//   d_in[1]: r_indices int32   [500000]
//   d_in[2]: c_indices int32   [500000]
//   d_in[3]: weight    float32 [256, 4]
// Output: float32 [500000, 4]
//
// R12 ncu: dur 107.7us, L1=65.7%, L2=39.4%, DRAM=34.4%, issue=41.6% —
// nothing saturated => latency-bound, MLP too low (4 loads/warp-iter).
// This version: 2 edges per warp iteration (8 independent LDG.128 -> MLP 8),
// int2 index loads, and a combined transpose-reduction: butterfly {16,8,4}
// on 8 accumulators (24 shfl), select by lane>>2, butterfly {2,1} (2 shfl)
// = 26 shfls per 2 edges (was 40). Output store becomes one contiguous
// 32B segment per pair. Occupancy 4->3 CTAs/SM (85-reg cap) traded for
// +50% outstanding loads per SM.

#define D 256

__global__ __launch_bounds__(256, 3)
void edge_mlp_kernel(const float* __restrict__ input,
                     const int* __restrict__ r_indices,
                     const int* __restrict__ c_indices,
                     const float* __restrict__ weight,
                     float* __restrict__ out,
                     int n_edges)
{
    const int lane   = threadIdx.x & 31;
    const int gwarp  = (blockIdx.x * blockDim.x + threadIdx.x) >> 5;
    const int nwarps = (gridDim.x * blockDim.x) >> 5;

    // Weight rows for this lane's dims, register-resident.
    // w[j]   -> row 4*lane + j        (dims [4l, 4l+4))
    // w[4+j] -> row 128 + 4*lane + j  (dims [128+4l, 128+4l+4))
    const float4* w4 = reinterpret_cast<const float4*>(weight);
    float4 w[8];
#pragma unroll
    for (int j = 0; j < 4; j++) w[j]     = w4[4 * lane + j];
#pragma unroll
    for (int j = 0; j < 4; j++) w[4 + j] = w4[128 + 4 * lane + j];

    const float4* in4 = reinterpret_cast<const float4*>(input);
    const int2*   r2  = reinterpret_cast<const int2*>(r_indices);
    const int2*   c2  = reinterpret_cast<const int2*>(c_indices);

    const int npairs = (n_edges + 1) >> 1;

    for (int p = gwarp; p < npairs; p += nwarps) {
        const int e0 = 2 * p;
        const int e1 = e0 + 1;

        int r0, c0, r1, c1;
        if (e1 < n_edges) {
            int2 rr = __ldg(&r2[p]);
            int2 cc = __ldg(&c2[p]);
            r0 = rr.x; r1 = rr.y; c0 = cc.x; c1 = cc.y;
        } else {
            r0 = __ldg(&r_indices[e0]);
            c0 = __ldg(&c_indices[e0]);
            r1 = r0; c1 = c0;  // duplicate work, store guarded below
        }

        // 8 independent, lane-consecutive (line-dense) float4 gathers.
        const float4* pa0 = in4 + (long long)r0 * (D / 4) + lane;
        const float4* pb0 = in4 + (long long)c0 * (D / 4) + lane;
        const float4* pa1 = in4 + (long long)r1 * (D / 4) + lane;
        const float4* pb1 = in4 + (long long)c1 * (D / 4) + lane;

        float4 a00 = pa0[0];
        float4 a01 = pa0[32];
        float4 b00 = pb0[0];
        float4 b01 = pb0[32];
        float4 a10 = pa1[0];
        float4 a11 = pa1[32];
        float4 b10 = pb1[0];
        float4 b11 = pb1[32];

        // Edge 0 accumulation
        float x0 = 0.f, y0 = 0.f, z0 = 0.f, u0 = 0.f;
        {
            float dv[8];
            dv[0] = fabsf(a00.x - b00.x);
            dv[1] = fabsf(a00.y - b00.y);
            dv[2] = fabsf(a00.z - b00.z);
            dv[3] = fabsf(a00.w - b00.w);
            dv[4] = fabsf(a01.x - b01.x);
            dv[5] = fabsf(a01.y - b01.y);
            dv[6] = fabsf(a01.z - b01.z);
            dv[7] = fabsf(a01.w - b01.w);
#pragma unroll
            for (int j = 0; j < 8; j++) {
                x0 = fmaf(dv[j], w[j].x, x0);
                y0 = fmaf(dv[j], w[j].y, y0);
                z0 = fmaf(dv[j], w[j].z, z0);
                u0 = fmaf(dv[j], w[j].w, u0);
            }
        }

        // Edge 1 accumulation
        float x1 = 0.f, y1 = 0.f, z1 = 0.f, u1 = 0.f;
        {
            float dv[8];
            dv[0] = fabsf(a10.x - b10.x);
            dv[1] = fabsf(a10.y - b10.y);
            dv[2] = fabsf(a10.z - b10.z);
            dv[3] = fabsf(a10.w - b10.w);
            dv[4] = fabsf(a11.x - b11.x);
            dv[5] = fabsf(a11.y - b11.y);
            dv[6] = fabsf(a11.z - b11.z);
            dv[7] = fabsf(a11.w - b11.w);
#pragma unroll
            for (int j = 0; j < 8; j++) {
                x1 = fmaf(dv[j], w[j].x, x1);
                y1 = fmaf(dv[j], w[j].y, y1);
                z1 = fmaf(dv[j], w[j].z, z1);
                u1 = fmaf(dv[j], w[j].w, u1);
            }
        }

        // Partial butterfly {16,8,4}: each lane ends with the mod-4
        // residue-class partial of all 8 values. 24 shfls.
#pragma unroll
        for (int off = 16; off >= 4; off >>= 1) {
            x0 += __shfl_xor_sync(0xFFFFFFFFu, x0, off);
            y0 += __shfl_xor_sync(0xFFFFFFFFu, y0, off);
            z0 += __shfl_xor_sync(0xFFFFFFFFu, z0, off);
            u0 += __shfl_xor_sync(0xFFFFFFFFu, u0, off);
            x1 += __shfl_xor_sync(0xFFFFFFFFu, x1, off);
            y1 += __shfl_xor_sync(0xFFFFFFFFu, y1, off);
            z1 += __shfl_xor_sync(0xFFFFFFFFu, z1, off);
            u1 += __shfl_xor_sync(0xFFFFFFFFu, u1, off);
        }

        // Lane group g = lane>>2 (4 lanes, residues 0..3) finalizes value g:
        // g 0..3 -> edge0 comps, g 4..7 -> edge1 comps.
        const int k = lane >> 2;
        float v = (k < 4) ? ((k < 2) ? (k == 0 ? x0 : y0)
                                     : (k == 2 ? z0 : u0))
                          : ((k < 6) ? (k == 4 ? x1 : y1)
                                     : (k == 6 ? z1 : u1));
        v += __shfl_xor_sync(0xFFFFFFFFu, v, 2);
        v += __shfl_xor_sync(0xFFFFFFFFu, v, 1);

        // Lanes 0,4,...,28 write out[e0*4 .. e0*4+7]: one 32B contiguous
        // segment (edge pair is adjacent in the output).
        if ((lane & 3) == 0) {
            if (k < 4) {
                out[(size_t)e0 * 4 + k] = v;
            } else if (e1 < n_edges) {
                out[(size_t)e1 * 4 + (k - 4)] = v;
            }
        }
    }
}

extern "C" void kernel_launch(void* const* d_in, const int* in_sizes, int n_in,
                              void* d_out, int out_size)
{
    const float* input  = (const float*)d_in[0];
    const int*   r_idx  = (const int*)d_in[1];
    const int*   c_idx  = (const int*)d_in[2];
    const float* weight = (const float*)d_in[3];
    float*       out    = (float*)d_out;

    const int n_edges = in_sizes[1];  // 500000

    const int threads = 256;
    const int blocks  = 148 * 16;

    edge_mlp_kernel<<<blocks, threads>>>(input, r_idx, c_idx, weight, out,
                                         n_edges);
}